// round 4
// baseline (speedup 1.0000x reference)
#include <cuda_runtime.h>

// ---------------- problem constants ----------------
#define NPC   16
#define FBP   8
#define CH    128
#define HH    96
#define H0    94          // after piece conv
#define H1    92          // after conv #1
#define H2    90          // after conv #2
#define FEAT  (CH*H2*H2)  // 1,036,800
#define OUTD  256
#define GCHUNK 4096
#define NBLK  ((FEAT + GCHUNK - 1) / GCHUNK)   // 254

typedef unsigned long long ull;

// ---------------- scratch (no allocation allowed) ----------------
__device__ float g_y0[CH * H0 * H0];
__device__ float g_y1[CH * H1 * H1];
__device__ float g_y2[CH * H2 * H2];
__device__ float g_part[NBLK * OUTD];

// ---------------- packed f32x2 helpers (sm_103a) ----------------
__device__ __forceinline__ ull pk(float lo, float hi) {
    ull r;
    asm("mov.b64 %0, {%1, %2};" : "=l"(r) : "f"(lo), "f"(hi));
    return r;
}
__device__ __forceinline__ void fma2(ull &d, ull a, ull b) {
    asm("fma.rn.f32x2 %0, %1, %2, %0;" : "+l"(d) : "l"(a), "l"(b));
}
__device__ __forceinline__ float2 up(ull v) {
    float x, y;
    asm("mov.b64 {%0, %1}, %2;" : "=f"(x), "=f"(y) : "l"(v));
    return make_float2(x, y);
}

// ---------------- kernel 1: grouped piece conv + bias + relu ----------------
// y0[(p*8+f), i, j] = relu(cat_b[p,f] + sum_{d: x[i+di,j+dj]==p} cat_w[p,f,d])
__global__ void piece_conv(const int* __restrict__ x, const float* __restrict__ cw,
                           const float* __restrict__ cb, float* __restrict__ y0) {
    __shared__ float sw[72];
    __shared__ float sb[8];
    int p = blockIdx.y;
    if (threadIdx.x < 72) sw[threadIdx.x] = cw[p * 72 + threadIdx.x];
    if (threadIdx.x < 8)  sb[threadIdx.x] = cb[p * 8 + threadIdx.x];
    __syncthreads();
    int pix = blockIdx.x * blockDim.x + threadIdx.x;
    if (pix >= H0 * H0) return;
    int i = pix / H0, j = pix % H0;
    float acc[FBP];
#pragma unroll
    for (int f = 0; f < FBP; f++) acc[f] = sb[f];
#pragma unroll
    for (int di = 0; di < 3; di++) {
#pragma unroll
        for (int dj = 0; dj < 3; dj++) {
            int v = x[(i + di) * HH + (j + dj)];
            if (v == p) {
#pragma unroll
                for (int f = 0; f < FBP; f++) acc[f] += sw[f * 9 + di * 3 + dj];
            }
        }
    }
#pragma unroll
    for (int f = 0; f < FBP; f++)
        y0[(p * FBP + f) * (H0 * H0) + pix] = fmaxf(acc[f], 0.f);
}

// ---------------- kernel 2/3: 128->128 3x3 VALID conv + bias + relu ----------------
// Tile: 4 rows x 16 cols of output, all 128 Cout. 256 threads:
//   thread owns 8 channels (co0..co0+7) x 4 pixels (2 f32x2 pixel-pairs).
#define CI_T 4
__global__ void __launch_bounds__(256) conv3x3(
    const float* __restrict__ in, const float* __restrict__ w,
    const float* __restrict__ b, float* __restrict__ out,
    int Hin, int Hout) {
    __shared__ __align__(16) float2 ws[CH * CI_T * 9];   // (co*CI_T+ci)*9+d, value=(w,w)  36.9KB
    __shared__ __align__(16) float  xs[CI_T][6][20];     // padded input patch

    int t = threadIdx.x;
    int co0  = (t >> 4) * 8;
    int pg   = t & 15;
    int prow = pg >> 2;
    int pcol = (pg & 3) * 4;
    int i0 = blockIdx.y * 4, j0 = blockIdx.x * 16;

    ull acc[8][2];
#pragma unroll
    for (int cr = 0; cr < 8; cr++) {
        float bv = b[co0 + cr];
        acc[cr][0] = pk(bv, bv);
        acc[cr][1] = pk(bv, bv);
    }

    for (int cib = 0; cib < CH; cib += CI_T) {
        __syncthreads();
        // stage weights, duplicated into both f32x2 lanes
        for (int idx = t; idx < CH * CI_T * 9; idx += 256) {
            int co = idx / (CI_T * 9);
            int r  = idx - co * (CI_T * 9);
            int ci = r / 9, d = r - ci * 9;
            float wv = w[(co * CH + cib + ci) * 9 + d];
            ws[idx] = make_float2(wv, wv);
        }
        // stage input patch (6 rows x 18 cols per ci), zero-fill OOB
        for (int idx = t; idx < CI_T * 6 * 18; idx += 256) {
            int ci  = idx / 108;
            int r   = idx - ci * 108;
            int row = r / 18, col = r - row * 18;
            int gi = i0 + row, gj = j0 + col;
            float v = (gi < Hin && gj < Hin)
                      ? in[(cib + ci) * Hin * Hin + gi * Hin + gj] : 0.f;
            xs[ci][row][col] = v;
        }
        __syncthreads();

#pragma unroll
        for (int ci = 0; ci < CI_T; ci++) {
#pragma unroll
            for (int di = 0; di < 3; di++) {
                const float* xr = &xs[ci][prow + di][pcol];
                float4 a4 = *(const float4*)xr;
                float2 b2 = *(const float2*)(xr + 4);
                float in6[6] = {a4.x, a4.y, a4.z, a4.w, b2.x, b2.y};
#pragma unroll
                for (int dj = 0; dj < 3; dj++) {
                    ull ip0 = pk(in6[dj],     in6[dj + 1]);
                    ull ip1 = pk(in6[dj + 2], in6[dj + 3]);
                    int wbase = co0 * (CI_T * 9) + ci * 9 + di * 3 + dj;
#pragma unroll
                    for (int cr = 0; cr < 8; cr++) {
                        ull wp = *(const ull*)&ws[wbase + cr * (CI_T * 9)];
                        fma2(acc[cr][0], wp, ip0);
                        fma2(acc[cr][1], wp, ip1);
                    }
                }
            }
        }
    }

    int oi = i0 + prow;
    if (oi < Hout) {
#pragma unroll
        for (int cr = 0; cr < 8; cr++) {
            float2 v0 = up(acc[cr][0]);
            float2 v1 = up(acc[cr][1]);
            float vals[4] = {v0.x, v0.y, v1.x, v1.y};
            long obase = (long)(co0 + cr) * Hout * Hout + (long)oi * Hout;
#pragma unroll
            for (int k = 0; k < 4; k++) {
                int oj = j0 + pcol + k;
                if (oj < Hout) out[obase + oj] = fmaxf(vals[k], 0.f);
            }
        }
    }
}

// ---------------- kernel 4: GEMV partials (DRAM-bound) ----------------
// Each block caches a GCHUNK slice of flat in SMEM; each warp privately owns
// rows o = warp, warp+8, ... (32 rows/warp) -> no atomics, deterministic.
__global__ void __launch_bounds__(256) gemv_kernel(
    const float* __restrict__ flat, const float* __restrict__ lw,
    float* __restrict__ part) {
    __shared__ __align__(16) float sx[GCHUNK];
    int bc = blockIdx.x;
    long base = (long)bc * GCHUNK;
    int n = FEAT - base;
    if (n > GCHUNK) n = GCHUNK;
    int n4 = n >> 2;

    const float4* xg  = (const float4*)(flat + base);
    float4*       sx4 = (float4*)sx;
    for (int k = threadIdx.x; k < n4; k += 256) sx4[k] = xg[k];
    __syncthreads();

    int wid  = threadIdx.x >> 5;
    int lane = threadIdx.x & 31;
    for (int o = wid; o < OUTD; o += 8) {
        const float4* wr = (const float4*)(lw + (size_t)o * FEAT + base);
        float s = 0.f;
#pragma unroll 8
        for (int k = lane; k < n4; k += 32) {
            float4 a = wr[k];
            float4 xv = sx4[k];
            s = fmaf(a.x, xv.x, s);
            s = fmaf(a.y, xv.y, s);
            s = fmaf(a.z, xv.z, s);
            s = fmaf(a.w, xv.w, s);
        }
#pragma unroll
        for (int off = 16; off; off >>= 1)
            s += __shfl_xor_sync(0xffffffffu, s, off);
        if (lane == 0) part[bc * OUTD + o] = s;
    }
}

// ---------------- kernel 5: deterministic final reduce + bias ----------------
__global__ void reduce_kernel(const float* __restrict__ part,
                              const float* __restrict__ lb,
                              float* __restrict__ out) {
    int o = threadIdx.x;
    float s0 = 0.f, s1 = 0.f, s2 = 0.f, s3 = 0.f;
    int c = 0;
    for (; c + 3 < NBLK; c += 4) {
        s0 += part[(c + 0) * OUTD + o];
        s1 += part[(c + 1) * OUTD + o];
        s2 += part[(c + 2) * OUTD + o];
        s3 += part[(c + 3) * OUTD + o];
    }
    for (; c < NBLK; c++) s0 += part[c * OUTD + o];
    out[o] = lb[o] + ((s0 + s1) + (s2 + s3));
}

// ---------------- launch ----------------
extern "C" void kernel_launch(void* const* d_in, const int* in_sizes, int n_in,
                              void* d_out, int out_size) {
    const int*   x      = (const int*)  d_in[0];
    const float* cat_w  = (const float*)d_in[1];
    const float* cat_b  = (const float*)d_in[2];
    const float* conv_w = (const float*)d_in[3];
    const float* conv_b = (const float*)d_in[4];
    const float* lin_w  = (const float*)d_in[5];
    const float* lin_b  = (const float*)d_in[6];
    float* out = (float*)d_out;

    float *y0, *y1, *y2, *part;
    cudaGetSymbolAddress((void**)&y0,   g_y0);
    cudaGetSymbolAddress((void**)&y1,   g_y1);
    cudaGetSymbolAddress((void**)&y2,   g_y2);
    cudaGetSymbolAddress((void**)&part, g_part);

    dim3 gA((H0 * H0 + 127) / 128, NPC);
    piece_conv<<<gA, 128>>>(x, cat_w, cat_b, y0);

    dim3 g1((H1 + 15) / 16, (H1 + 3) / 4);
    conv3x3<<<g1, 256>>>(y0, conv_w, conv_b, y1, H0, H1);

    dim3 g2((H2 + 15) / 16, (H2 + 3) / 4);
    conv3x3<<<g2, 256>>>(y1, conv_w, conv_b, y2, H1, H2);

    gemv_kernel<<<NBLK, 256>>>(y2, lin_w, part);
    reduce_kernel<<<1, OUTD>>>(part, lin_b, out);
}

// round 5
// speedup vs baseline: 1.1676x; 1.1676x over previous
#include <cuda_runtime.h>

// ---------------- problem constants ----------------
#define NPC   16
#define FBP   8
#define CH    128
#define HH    96
#define H0    94          // after piece conv
#define H1    92          // after conv #1
#define H2    90          // after conv #2
#define FEAT  (CH*H2*H2)  // 1,036,800
#define OUTD  256
#define GCHUNK 4096
#define NBLK  ((FEAT + GCHUNK - 1) / GCHUNK)   // 254

typedef unsigned long long ull;

// ---------------- scratch (no allocation allowed) ----------------
__device__ float g_y0[CH * H0 * H0];
__device__ float g_y1[CH * H1 * H1];
__device__ float g_y2[CH * H2 * H2];
__device__ float g_part[NBLK * OUTD];

// ---------------- packed f32x2 helpers (sm_103a) ----------------
__device__ __forceinline__ ull pk(float lo, float hi) {
    ull r;
    asm("mov.b64 %0, {%1, %2};" : "=l"(r) : "f"(lo), "f"(hi));
    return r;
}
__device__ __forceinline__ void fma2(ull &d, ull a, ull b) {
    asm("fma.rn.f32x2 %0, %1, %2, %0;" : "+l"(d) : "l"(a), "l"(b));
}
__device__ __forceinline__ float2 up(ull v) {
    float x, y;
    asm("mov.b64 {%0, %1}, %2;" : "=f"(x), "=f"(y) : "l"(v));
    return make_float2(x, y);
}

// ---------------- kernel 1: grouped piece conv + bias + relu ----------------
__global__ void piece_conv(const int* __restrict__ x, const float* __restrict__ cw,
                           const float* __restrict__ cb, float* __restrict__ y0) {
    __shared__ float sw[72];
    __shared__ float sb[8];
    int p = blockIdx.y;
    if (threadIdx.x < 72) sw[threadIdx.x] = cw[p * 72 + threadIdx.x];
    if (threadIdx.x < 8)  sb[threadIdx.x] = cb[p * 8 + threadIdx.x];
    __syncthreads();
    int pix = blockIdx.x * blockDim.x + threadIdx.x;
    if (pix >= H0 * H0) return;
    int i = pix / H0, j = pix % H0;
    float acc[FBP];
#pragma unroll
    for (int f = 0; f < FBP; f++) acc[f] = sb[f];
#pragma unroll
    for (int di = 0; di < 3; di++) {
#pragma unroll
        for (int dj = 0; dj < 3; dj++) {
            int v = x[(i + di) * HH + (j + dj)];
            if (v == p) {
#pragma unroll
                for (int f = 0; f < FBP; f++) acc[f] += sw[f * 9 + di * 3 + dj];
            }
        }
    }
#pragma unroll
    for (int f = 0; f < FBP; f++)
        y0[(p * FBP + f) * (H0 * H0) + pix] = fmaxf(acc[f], 0.f);
}

// ---------------- kernel 2/3: 128->128 3x3 VALID conv + bias + relu ----------------
// Tile: 4 rows x 16 cols of output, all 128 Cout. 256 threads:
//   thread owns 4 Cout (co0..co0+3) x 8 pixels (4 f32x2 pixel-pairs).
//   Each weight LDS.64 feeds 4 FMA2s -> FMA-pipe bound.
#define CI_T 4
__global__ void __launch_bounds__(256) conv3x3(
    const float* __restrict__ in, const float* __restrict__ w,
    const float* __restrict__ b, float* __restrict__ out,
    int Hin, int Hout) {
    __shared__ __align__(16) float2 ws[CH * CI_T * 9];   // (co*CI_T+ci)*9+d, value=(w,w)
    __shared__ __align__(16) float  xs[CI_T][6][20];     // padded input patch

    int t = threadIdx.x;
    int co0  = (t >> 3) * 4;          // 32 groups of 4 consecutive Cout
    int pg   = t & 7;                 // 8 pixel groups of 8 pixels
    int prow = pg >> 1;               // 0..3
    int pcol = (pg & 1) * 8;          // 0 or 8
    int i0 = blockIdx.y * 4, j0 = blockIdx.x * 16;

    ull acc[4][4];
#pragma unroll
    for (int cr = 0; cr < 4; cr++) {
        float bv = b[co0 + cr];
        ull bp = pk(bv, bv);
#pragma unroll
        for (int j = 0; j < 4; j++) acc[cr][j] = bp;
    }

    for (int cib = 0; cib < CH; cib += CI_T) {
        __syncthreads();
        // stage weights, duplicated into both f32x2 lanes
        for (int idx = t; idx < CH * CI_T * 9; idx += 256) {
            int co = idx / (CI_T * 9);
            int r  = idx - co * (CI_T * 9);
            int ci = r / 9, d = r - ci * 9;
            float wv = w[(co * CH + cib + ci) * 9 + d];
            ws[idx] = make_float2(wv, wv);
        }
        // stage input patch (6 rows x 18 cols per ci), zero-fill OOB
        for (int idx = t; idx < CI_T * 6 * 18; idx += 256) {
            int ci  = idx / 108;
            int r   = idx - ci * 108;
            int row = r / 18, col = r - row * 18;
            int gi = i0 + row, gj = j0 + col;
            float v = (gi < Hin && gj < Hin)
                      ? in[(cib + ci) * Hin * Hin + gi * Hin + gj] : 0.f;
            xs[ci][row][col] = v;
        }
        __syncthreads();

#pragma unroll
        for (int ci = 0; ci < CI_T; ci++) {
#pragma unroll
            for (int di = 0; di < 3; di++) {
                const float* xr = &xs[ci][prow + di][pcol];
                float4 a4 = *(const float4*)xr;
                float4 b4 = *(const float4*)(xr + 4);
                float2 c2 = *(const float2*)(xr + 8);
                float in10[10] = {a4.x, a4.y, a4.z, a4.w,
                                  b4.x, b4.y, b4.z, b4.w, c2.x, c2.y};
#pragma unroll
                for (int dj = 0; dj < 3; dj++) {
                    ull ip0 = pk(in10[dj],     in10[dj + 1]);
                    ull ip1 = pk(in10[dj + 2], in10[dj + 3]);
                    ull ip2 = pk(in10[dj + 4], in10[dj + 5]);
                    ull ip3 = pk(in10[dj + 6], in10[dj + 7]);
                    int wbase = co0 * (CI_T * 9) + ci * 9 + di * 3 + dj;
#pragma unroll
                    for (int cr = 0; cr < 4; cr++) {
                        ull wp = *(const ull*)&ws[wbase + cr * (CI_T * 9)];
                        fma2(acc[cr][0], wp, ip0);
                        fma2(acc[cr][1], wp, ip1);
                        fma2(acc[cr][2], wp, ip2);
                        fma2(acc[cr][3], wp, ip3);
                    }
                }
            }
        }
    }

    int oi = i0 + prow;
    if (oi < Hout) {
#pragma unroll
        for (int cr = 0; cr < 4; cr++) {
            float vals[8];
#pragma unroll
            for (int j = 0; j < 4; j++) {
                float2 v = up(acc[cr][j]);
                vals[2 * j]     = v.x;
                vals[2 * j + 1] = v.y;
            }
            long obase = (long)(co0 + cr) * Hout * Hout + (long)oi * Hout;
#pragma unroll
            for (int k = 0; k < 8; k++) {
                int oj = j0 + pcol + k;
                if (oj < Hout) out[obase + oj] = fmaxf(vals[k], 0.f);
            }
        }
    }
}

// ---------------- kernel 4: GEMV partials (DRAM-bound) ----------------
// grid = (NBLK, 2). Each block caches a GCHUNK slice of flat in SMEM and
// handles 128 of the 256 output rows. Each warp owns 16 rows, processed
// 4 at a time -> 4 independent weight LDG streams per iteration, one
// pipeline drain per 4 rows. No atomics, fully deterministic.
__global__ void __launch_bounds__(256) gemv_kernel(
    const float* __restrict__ flat, const float* __restrict__ lw,
    float* __restrict__ part) {
    __shared__ __align__(16) float sx[GCHUNK];
    int bc = blockIdx.x;
    long base = (long)bc * GCHUNK;
    int n = FEAT - base;
    if (n > GCHUNK) n = GCHUNK;
    int n4 = n >> 2;

    const float4* xg  = (const float4*)(flat + base);
    float4*       sx4 = (float4*)sx;
    for (int k = threadIdx.x; k < n4; k += 256) sx4[k] = xg[k];
    __syncthreads();

    int wid  = threadIdx.x >> 5;
    int lane = threadIdx.x & 31;
    int rbase = blockIdx.y * 128 + wid * 16;

    for (int g = 0; g < 4; g++) {
        int o = rbase + g * 4;
        const float4* w0 = (const float4*)(lw + (size_t)(o + 0) * FEAT + base);
        const float4* w1 = (const float4*)(lw + (size_t)(o + 1) * FEAT + base);
        const float4* w2 = (const float4*)(lw + (size_t)(o + 2) * FEAT + base);
        const float4* w3 = (const float4*)(lw + (size_t)(o + 3) * FEAT + base);
        float s0 = 0.f, s1 = 0.f, s2 = 0.f, s3 = 0.f;
#pragma unroll 2
        for (int k = lane; k < n4; k += 32) {
            float4 xv = sx4[k];
            float4 a0 = w0[k];
            float4 a1 = w1[k];
            float4 a2 = w2[k];
            float4 a3 = w3[k];
            s0 = fmaf(a0.x, xv.x, s0); s0 = fmaf(a0.y, xv.y, s0);
            s0 = fmaf(a0.z, xv.z, s0); s0 = fmaf(a0.w, xv.w, s0);
            s1 = fmaf(a1.x, xv.x, s1); s1 = fmaf(a1.y, xv.y, s1);
            s1 = fmaf(a1.z, xv.z, s1); s1 = fmaf(a1.w, xv.w, s1);
            s2 = fmaf(a2.x, xv.x, s2); s2 = fmaf(a2.y, xv.y, s2);
            s2 = fmaf(a2.z, xv.z, s2); s2 = fmaf(a2.w, xv.w, s2);
            s3 = fmaf(a3.x, xv.x, s3); s3 = fmaf(a3.y, xv.y, s3);
            s3 = fmaf(a3.z, xv.z, s3); s3 = fmaf(a3.w, xv.w, s3);
        }
#pragma unroll
        for (int off = 16; off; off >>= 1) {
            s0 += __shfl_xor_sync(0xffffffffu, s0, off);
            s1 += __shfl_xor_sync(0xffffffffu, s1, off);
            s2 += __shfl_xor_sync(0xffffffffu, s2, off);
            s3 += __shfl_xor_sync(0xffffffffu, s3, off);
        }
        if (lane == 0) {
            part[bc * OUTD + o + 0] = s0;
            part[bc * OUTD + o + 1] = s1;
            part[bc * OUTD + o + 2] = s2;
            part[bc * OUTD + o + 3] = s3;
        }
    }
}

// ---------------- kernel 5: deterministic final reduce + bias ----------------
__global__ void reduce_kernel(const float* __restrict__ part,
                              const float* __restrict__ lb,
                              float* __restrict__ out) {
    int o = threadIdx.x;
    float s0 = 0.f, s1 = 0.f, s2 = 0.f, s3 = 0.f;
    int c = 0;
    for (; c + 3 < NBLK; c += 4) {
        s0 += part[(c + 0) * OUTD + o];
        s1 += part[(c + 1) * OUTD + o];
        s2 += part[(c + 2) * OUTD + o];
        s3 += part[(c + 3) * OUTD + o];
    }
    for (; c < NBLK; c++) s0 += part[c * OUTD + o];
    out[o] = lb[o] + ((s0 + s1) + (s2 + s3));
}

// ---------------- launch ----------------
extern "C" void kernel_launch(void* const* d_in, const int* in_sizes, int n_in,
                              void* d_out, int out_size) {
    const int*   x      = (const int*)  d_in[0];
    const float* cat_w  = (const float*)d_in[1];
    const float* cat_b  = (const float*)d_in[2];
    const float* conv_w = (const float*)d_in[3];
    const float* conv_b = (const float*)d_in[4];
    const float* lin_w  = (const float*)d_in[5];
    const float* lin_b  = (const float*)d_in[6];
    float* out = (float*)d_out;

    float *y0, *y1, *y2, *part;
    cudaGetSymbolAddress((void**)&y0,   g_y0);
    cudaGetSymbolAddress((void**)&y1,   g_y1);
    cudaGetSymbolAddress((void**)&y2,   g_y2);
    cudaGetSymbolAddress((void**)&part, g_part);

    dim3 gA((H0 * H0 + 127) / 128, NPC);
    piece_conv<<<gA, 128>>>(x, cat_w, cat_b, y0);

    dim3 g1((H1 + 15) / 16, (H1 + 3) / 4);
    conv3x3<<<g1, 256>>>(y0, conv_w, conv_b, y1, H0, H1);

    dim3 g2((H2 + 15) / 16, (H2 + 3) / 4);
    conv3x3<<<g2, 256>>>(y1, conv_w, conv_b, y2, H1, H2);

    dim3 gg(NBLK, 2);
    gemv_kernel<<<gg, 256>>>(y2, lin_w, part);
    reduce_kernel<<<1, OUTD>>>(part, lin_b, out);
}

// round 7
// speedup vs baseline: 1.3566x; 1.1619x over previous
#include <cuda_runtime.h>

// ---------------- problem constants ----------------
#define NPC   16
#define FBP   8
#define CH    128
#define HH    96
#define H0    94          // after piece conv
#define H1    92          // after conv #1
#define H2    90          // after conv #2
#define FEAT  (CH*H2*H2)  // 1,036,800
#define OUTD  256
#define GCHUNK 4096
#define NBLK  ((FEAT + GCHUNK - 1) / GCHUNK)   // 254

typedef unsigned long long ull;

// ---------------- scratch (no allocation allowed) ----------------
__device__ float g_y0[CH * H0 * H0];
__device__ float g_y1[CH * H1 * H1];
__device__ float g_y2[CH * H2 * H2];
__device__ float g_part[NBLK * OUTD];

// ---------------- packed f32x2 helpers (sm_103a) ----------------
__device__ __forceinline__ ull pk(float lo, float hi) {
    ull r;
    asm("mov.b64 %0, {%1, %2};" : "=l"(r) : "f"(lo), "f"(hi));
    return r;
}
__device__ __forceinline__ void fma2(ull &d, ull a, ull b) {
    asm("fma.rn.f32x2 %0, %1, %2, %0;" : "+l"(d) : "l"(a), "l"(b));
}
__device__ __forceinline__ float2 up(ull v) {
    float x, y;
    asm("mov.b64 {%0, %1}, %2;" : "=f"(x), "=f"(y) : "l"(v));
    return make_float2(x, y);
}

// ---------------- kernel 1: grouped piece conv + bias + relu ----------------
__global__ void piece_conv(const int* __restrict__ x, const float* __restrict__ cw,
                           const float* __restrict__ cb, float* __restrict__ y0) {
    __shared__ float sw[72];
    __shared__ float sb[8];
    int p = blockIdx.y;
    if (threadIdx.x < 72) sw[threadIdx.x] = cw[p * 72 + threadIdx.x];
    if (threadIdx.x < 8)  sb[threadIdx.x] = cb[p * 8 + threadIdx.x];
    __syncthreads();
    int pix = blockIdx.x * blockDim.x + threadIdx.x;
    if (pix >= H0 * H0) return;
    int i = pix / H0, j = pix % H0;
    float acc[FBP];
#pragma unroll
    for (int f = 0; f < FBP; f++) acc[f] = sb[f];
#pragma unroll
    for (int di = 0; di < 3; di++) {
#pragma unroll
        for (int dj = 0; dj < 3; dj++) {
            int v = x[(i + di) * HH + (j + dj)];
            if (v == p) {
#pragma unroll
                for (int f = 0; f < FBP; f++) acc[f] += sw[f * 9 + di * 3 + dj];
            }
        }
    }
#pragma unroll
    for (int f = 0; f < FBP; f++)
        y0[(p * FBP + f) * (H0 * H0) + pix] = fmaxf(acc[f], 0.f);
}

// ---------------- kernel 2/3: 128->128 3x3 VALID conv + bias + relu ----------------
// Tile: 4 rows x 16 cols of output, 64 Cout per block (z = Cout half).
// Grid = 6 x 23 x 2 = 276 blocks (~2/SM -> staging latency overlapped).
// 256 threads: thread owns 2 Cout x 8 pixels (4 f32x2 pairs).
#define CI_T 4
#define WS_STRIDE 37   // float2 per local-Cout row (36 used + 1 pad, kills LDS.64 conflicts)
__global__ void __launch_bounds__(256) conv3x3(
    const float* __restrict__ in, const float* __restrict__ w,
    const float* __restrict__ b, float* __restrict__ out,
    int Hin, int Hout) {
    __shared__ __align__(16) float2 ws[64 * WS_STRIDE];  // ~19 KB
    __shared__ __align__(16) float  xs[CI_T][6][20];

    int t = threadIdx.x;
    int co_g = t >> 3;                // 0..31 -> 2 Cout each
    int pg   = t & 7;
    int prow = pg >> 1;               // 0..3
    int pcol = (pg & 1) * 8;          // 0 or 8
    int i0 = blockIdx.y * 4, j0 = blockIdx.x * 16;
    int zc = blockIdx.z * 64;         // Cout base of this half

    ull acc[2][4];
#pragma unroll
    for (int cr = 0; cr < 2; cr++) {
        float bv = b[zc + co_g * 2 + cr];
        ull bp = pk(bv, bv);
#pragma unroll
        for (int j = 0; j < 4; j++) acc[cr][j] = bp;
    }

    for (int cib = 0; cib < CH; cib += CI_T) {
        __syncthreads();
        // stage weights for 64 local Cout x CI_T ci x 9 taps, duplicated lanes
        for (int idx = t; idx < 64 * CI_T * 9; idx += 256) {
            int lc = idx / (CI_T * 9);
            int r  = idx - lc * (CI_T * 9);
            int ci = r / 9, d = r - ci * 9;
            float wv = w[((zc + lc) * CH + cib + ci) * 9 + d];
            ws[lc * WS_STRIDE + r] = make_float2(wv, wv);
        }
        // stage input patch (6 rows x 18 cols per ci), zero-fill OOB
        for (int idx = t; idx < CI_T * 6 * 18; idx += 256) {
            int ci  = idx / 108;
            int r   = idx - ci * 108;
            int row = r / 18, col = r - row * 18;
            int gi = i0 + row, gj = j0 + col;
            float v = (gi < Hin && gj < Hin)
                      ? in[(cib + ci) * Hin * Hin + gi * Hin + gj] : 0.f;
            xs[ci][row][col] = v;
        }
        __syncthreads();

#pragma unroll
        for (int ci = 0; ci < CI_T; ci++) {
#pragma unroll
            for (int di = 0; di < 3; di++) {
                const float* xr = &xs[ci][prow + di][pcol];
                float4 a4 = *(const float4*)xr;
                float4 b4 = *(const float4*)(xr + 4);
                float2 c2 = *(const float2*)(xr + 8);
                float in10[10] = {a4.x, a4.y, a4.z, a4.w,
                                  b4.x, b4.y, b4.z, b4.w, c2.x, c2.y};
#pragma unroll
                for (int dj = 0; dj < 3; dj++) {
                    ull ip0 = pk(in10[dj],     in10[dj + 1]);
                    ull ip1 = pk(in10[dj + 2], in10[dj + 3]);
                    ull ip2 = pk(in10[dj + 4], in10[dj + 5]);
                    ull ip3 = pk(in10[dj + 6], in10[dj + 7]);
                    int wb = ci * 9 + di * 3 + dj;
#pragma unroll
                    for (int cr = 0; cr < 2; cr++) {
                        ull wp = *(const ull*)&ws[(co_g * 2 + cr) * WS_STRIDE + wb];
                        fma2(acc[cr][0], wp, ip0);
                        fma2(acc[cr][1], wp, ip1);
                        fma2(acc[cr][2], wp, ip2);
                        fma2(acc[cr][3], wp, ip3);
                    }
                }
            }
        }
    }

    int oi = i0 + prow;
    if (oi < Hout) {
#pragma unroll
        for (int cr = 0; cr < 2; cr++) {
            float vals[8];
#pragma unroll
            for (int j = 0; j < 4; j++) {
                float2 v = up(acc[cr][j]);
                vals[2 * j]     = v.x;
                vals[2 * j + 1] = v.y;
            }
            long obase = (long)(zc + co_g * 2 + cr) * Hout * Hout + (long)oi * Hout;
#pragma unroll
            for (int k = 0; k < 8; k++) {
                int oj = j0 + pcol + k;
                if (oj < Hout) out[obase + oj] = fmaxf(vals[k], 0.f);
            }
        }
    }
}

// ---------------- kernel 4: GEMV partials (DRAM-bound) ----------------
// grid = (NBLK, 2). Block caches a GCHUNK slice in SMEM, handles 128 rows.
// Warp owns 16 rows, 4 at a time; inner loop does 4 k-steps x 4 rows =
// 16 LDG.128 in flight before any FMA dependency. n4 in {1024,128}, both
// multiples of 128, so the 4-deep sub-step structure has no remainder.
__global__ void __launch_bounds__(256) gemv_kernel(
    const float* __restrict__ flat, const float* __restrict__ lw,
    float* __restrict__ part) {
    __shared__ __align__(16) float sx[GCHUNK];
    int bc = blockIdx.x;
    long base = (long)bc * GCHUNK;
    int n = FEAT - base;
    if (n > GCHUNK) n = GCHUNK;
    int n4 = n >> 2;

    const float4* xg  = (const float4*)(flat + base);
    float4*       sx4 = (float4*)sx;
    for (int k = threadIdx.x; k < n4; k += 256) sx4[k] = xg[k];
    __syncthreads();

    int wid  = threadIdx.x >> 5;
    int lane = threadIdx.x & 31;
    int rbase = blockIdx.y * 128 + wid * 16;

    for (int g = 0; g < 4; g++) {
        int o = rbase + g * 4;
        const float4* w0 = (const float4*)(lw + (size_t)(o + 0) * FEAT + base);
        const float4* w1 = (const float4*)(lw + (size_t)(o + 1) * FEAT + base);
        const float4* w2 = (const float4*)(lw + (size_t)(o + 2) * FEAT + base);
        const float4* w3 = (const float4*)(lw + (size_t)(o + 3) * FEAT + base);
        float s0 = 0.f, s1 = 0.f, s2 = 0.f, s3 = 0.f;
        for (int k = lane; k < n4; k += 128) {
            float4 a[4][4];
#pragma unroll
            for (int j = 0; j < 4; j++) {
                int kk = k + 32 * j;
                a[0][j] = w0[kk];
                a[1][j] = w1[kk];
                a[2][j] = w2[kk];
                a[3][j] = w3[kk];
            }
#pragma unroll
            for (int j = 0; j < 4; j++) {
                float4 xv = sx4[k + 32 * j];
                s0 = fmaf(a[0][j].x, xv.x, s0); s0 = fmaf(a[0][j].y, xv.y, s0);
                s0 = fmaf(a[0][j].z, xv.z, s0); s0 = fmaf(a[0][j].w, xv.w, s0);
                s1 = fmaf(a[1][j].x, xv.x, s1); s1 = fmaf(a[1][j].y, xv.y, s1);
                s1 = fmaf(a[1][j].z, xv.z, s1); s1 = fmaf(a[1][j].w, xv.w, s1);
                s2 = fmaf(a[2][j].x, xv.x, s2); s2 = fmaf(a[2][j].y, xv.y, s2);
                s2 = fmaf(a[2][j].z, xv.z, s2); s2 = fmaf(a[2][j].w, xv.w, s2);
                s3 = fmaf(a[3][j].x, xv.x, s3); s3 = fmaf(a[3][j].y, xv.y, s3);
                s3 = fmaf(a[3][j].z, xv.z, s3); s3 = fmaf(a[3][j].w, xv.w, s3);
            }
        }
#pragma unroll
        for (int off = 16; off; off >>= 1) {
            s0 += __shfl_xor_sync(0xffffffffu, s0, off);
            s1 += __shfl_xor_sync(0xffffffffu, s1, off);
            s2 += __shfl_xor_sync(0xffffffffu, s2, off);
            s3 += __shfl_xor_sync(0xffffffffu, s3, off);
        }
        if (lane == 0) {
            part[bc * OUTD + o + 0] = s0;
            part[bc * OUTD + o + 1] = s1;
            part[bc * OUTD + o + 2] = s2;
            part[bc * OUTD + o + 3] = s3;
        }
    }
}

// ---------------- kernel 5: parallel deterministic reduce + bias ----------------
// 32 blocks x 8 warps; warp w of block b owns output o = b*8 + w.
__global__ void reduce_kernel(const float* __restrict__ part,
                              const float* __restrict__ lb,
                              float* __restrict__ out) {
    int o = blockIdx.x * 8 + (threadIdx.x >> 5);
    int lane = threadIdx.x & 31;
    float s = 0.f;
    for (int c = lane; c < NBLK; c += 32) s += part[c * OUTD + o];
#pragma unroll
    for (int off = 16; off; off >>= 1)
        s += __shfl_xor_sync(0xffffffffu, s, off);
    if (lane == 0) out[o] = lb[o] + s;
}

// ---------------- launch ----------------
extern "C" void kernel_launch(void* const* d_in, const int* in_sizes, int n_in,
                              void* d_out, int out_size) {
    const int*   x      = (const int*)  d_in[0];
    const float* cat_w  = (const float*)d_in[1];
    const float* cat_b  = (const float*)d_in[2];
    const float* conv_w = (const float*)d_in[3];
    const float* conv_b = (const float*)d_in[4];
    const float* lin_w  = (const float*)d_in[5];
    const float* lin_b  = (const float*)d_in[6];
    float* out = (float*)d_out;

    float *y0, *y1, *y2, *part;
    cudaGetSymbolAddress((void**)&y0,   g_y0);
    cudaGetSymbolAddress((void**)&y1,   g_y1);
    cudaGetSymbolAddress((void**)&y2,   g_y2);
    cudaGetSymbolAddress((void**)&part, g_part);

    dim3 gA((H0 * H0 + 127) / 128, NPC);
    piece_conv<<<gA, 128>>>(x, cat_w, cat_b, y0);

    dim3 g1((H1 + 15) / 16, (H1 + 3) / 4, 2);
    conv3x3<<<g1, 256>>>(y0, conv_w, conv_b, y1, H0, H1);

    dim3 g2((H2 + 15) / 16, (H2 + 3) / 4, 2);
    conv3x3<<<g2, 256>>>(y1, conv_w, conv_b, y2, H1, H2);

    dim3 gg(NBLK, 2);
    gemv_kernel<<<gg, 256>>>(y2, lin_w, part);
    reduce_kernel<<<32, 256>>>(part, lin_b, out);
}

// round 8
// speedup vs baseline: 1.7288x; 1.2743x over previous
#include <cuda_runtime.h>

// ---------------- problem constants ----------------
#define NPC   16
#define FBP   8
#define CH    128
#define HH    96
#define H0    94          // after piece conv
#define H1    92          // after conv #1
#define H2    90          // after conv #2
#define FEAT  (CH*H2*H2)  // 1,036,800
#define OUTD  256
#define GCHUNK 4096
#define NBLK  ((FEAT + GCHUNK - 1) / GCHUNK)   // 254

typedef unsigned long long ull;

// ---------------- scratch (no allocation allowed) ----------------
__device__ float g_y0[CH * H0 * H0];
__device__ float g_y1[CH * H1 * H1];
__device__ float g_y2[CH * H2 * H2];
__device__ float g_part[NBLK * OUTD];

// ---------------- packed f32x2 helpers (sm_103a) ----------------
__device__ __forceinline__ ull pk(float lo, float hi) {
    ull r;
    asm("mov.b64 %0, {%1, %2};" : "=l"(r) : "f"(lo), "f"(hi));
    return r;
}
__device__ __forceinline__ void fma2(ull &d, ull a, ull b) {
    asm("fma.rn.f32x2 %0, %1, %2, %0;" : "+l"(d) : "l"(a), "l"(b));
}
__device__ __forceinline__ float2 up(ull v) {
    float x, y;
    asm("mov.b64 {%0, %1}, %2;" : "=f"(x), "=f"(y) : "l"(v));
    return make_float2(x, y);
}

// ---------------- kernel 1: grouped piece conv + bias + relu ----------------
__global__ void piece_conv(const int* __restrict__ x, const float* __restrict__ cw,
                           const float* __restrict__ cb, float* __restrict__ y0) {
    __shared__ float sw[72];
    __shared__ float sb[8];
    int p = blockIdx.y;
    if (threadIdx.x < 72) sw[threadIdx.x] = cw[p * 72 + threadIdx.x];
    if (threadIdx.x < 8)  sb[threadIdx.x] = cb[p * 8 + threadIdx.x];
    __syncthreads();
    int pix = blockIdx.x * blockDim.x + threadIdx.x;
    if (pix >= H0 * H0) return;
    int i = pix / H0, j = pix % H0;
    float acc[FBP];
#pragma unroll
    for (int f = 0; f < FBP; f++) acc[f] = sb[f];
#pragma unroll
    for (int di = 0; di < 3; di++) {
#pragma unroll
        for (int dj = 0; dj < 3; dj++) {
            int v = x[(i + di) * HH + (j + dj)];
            if (v == p) {
#pragma unroll
                for (int f = 0; f < FBP; f++) acc[f] += sw[f * 9 + di * 3 + dj];
            }
        }
    }
#pragma unroll
    for (int f = 0; f < FBP; f++)
        y0[(p * FBP + f) * (H0 * H0) + pix] = fmaxf(acc[f], 0.f);
}

// ---------------- kernel 2/3: 128->128 3x3 VALID conv + bias + relu ----------------
// Tile: 4 rows x 16 cols output, 64 Cout per block (z = Cout half). 256 threads.
// Thread owns 2 Cout x (2 row-paired f32x2) x 4 cols = 16 output px.
// Input SMEM pre-packed as float2 = (x[r][c], x[r+2][c]) -> inner loop has
// ZERO pack instructions; operands come straight from LDS.128.
// Staging is software-pipelined: next cib's weights/x prefetched to registers.
#define CI_T 4
#define WS_STRIDE 37   // float2 per local-Cout row (36 used + 1 pad)
__global__ void __launch_bounds__(256, 2) conv3x3(
    const float* __restrict__ in, const float* __restrict__ w,
    const float* __restrict__ b, float* __restrict__ out,
    int Hin, int Hout) {
    __shared__ __align__(16) float2 ws[64 * WS_STRIDE];
    __shared__ __align__(16) float2 xp[CI_T * 4 * 18];   // [ci][rowpair 0..3][col 0..17]

    int t = threadIdx.x;
    int co_g = t >> 3;                // 0..31 -> 2 Cout each
    int pg   = t & 7;
    int rp   = pg & 1;                // row-pair select: rows (rp, rp+2)
    int cg   = pg >> 1;               // 0..3 -> 4 cols each
    int i0 = blockIdx.y * 4, j0 = blockIdx.x * 16;
    int zc = blockIdx.z * 64;

    // ---- constant per-thread staging maps ----
    // weights: 64*36 = 2304 scalars = exactly 9 per thread
    int wg_off[9], ws_off[9];
#pragma unroll
    for (int k = 0; k < 9; k++) {
        int idx = t + 256 * k;
        int lc = idx / 36, r = idx - lc * 36;
        int ci = r / 9,   d = r - ci * 9;
        wg_off[k] = ((zc + lc) * CH + ci) * 9 + d;   // + cib*9 at load time
        ws_off[k] = lc * WS_STRIDE + r;
    }
    // x: 4*4*18 = 288 float2 entries; entry idx = t (all) and t+256 (t<32)
    int xg_off[2], xci[2];
    unsigned char xva[2], xvb[2];
#pragma unroll
    for (int e = 0; e < 2; e++) {
        int idx = t + 256 * e;
        int ci = idx / 72, rem = idx - ci * 72;
        int rr = rem / 18, c = rem - rr * 18;
        int gi = i0 + rr, gj = j0 + c;
        xci[e] = ci;
        xg_off[e] = gi * Hin + gj;
        xva[e] = (gi < Hin && gj < Hin);
        xvb[e] = (gi + 2 < Hin && gj < Hin);
    }

    float  wreg[9];
    float2 xreg[2];
    // prologue: prefetch cib = 0
#pragma unroll
    for (int k = 0; k < 9; k++) wreg[k] = __ldg(&w[wg_off[k]]);
    {
        const float* p0 = in + xci[0] * Hin * Hin + xg_off[0];
        xreg[0].x = xva[0] ? __ldg(p0) : 0.f;
        xreg[0].y = xvb[0] ? __ldg(p0 + 2 * Hin) : 0.f;
        if (t < 32) {
            const float* p1 = in + xci[1] * Hin * Hin + xg_off[1];
            xreg[1].x = xva[1] ? __ldg(p1) : 0.f;
            xreg[1].y = xvb[1] ? __ldg(p1 + 2 * Hin) : 0.f;
        }
    }

    ull acc[2][4];
#pragma unroll
    for (int cr = 0; cr < 2; cr++) {
        float bv = b[zc + co_g * 2 + cr];
        ull bp = pk(bv, bv);
#pragma unroll
        for (int c = 0; c < 4; c++) acc[cr][c] = bp;
    }

    for (int cib = 0; cib < CH; cib += CI_T) {
        __syncthreads();
#pragma unroll
        for (int k = 0; k < 9; k++)
            ws[ws_off[k]] = make_float2(wreg[k], wreg[k]);
        xp[t] = xreg[0];
        if (t < 32) xp[t + 256] = xreg[1];
        __syncthreads();

        if (cib + CI_T < CH) {
            int nb = cib + CI_T;
#pragma unroll
            for (int k = 0; k < 9; k++)
                wreg[k] = __ldg(&w[wg_off[k] + nb * 9]);
            const float* p0 = in + (nb + xci[0]) * Hin * Hin + xg_off[0];
            xreg[0].x = xva[0] ? __ldg(p0) : 0.f;
            xreg[0].y = xvb[0] ? __ldg(p0 + 2 * Hin) : 0.f;
            if (t < 32) {
                const float* p1 = in + (nb + xci[1]) * Hin * Hin + xg_off[1];
                xreg[1].x = xva[1] ? __ldg(p1) : 0.f;
                xreg[1].y = xvb[1] ? __ldg(p1 + 2 * Hin) : 0.f;
            }
        }

#pragma unroll
        for (int ci = 0; ci < CI_T; ci++) {
#pragma unroll
            for (int di = 0; di < 3; di++) {
                const ulonglong2* xr =
                    (const ulonglong2*)&xp[ci * 72 + (rp + di) * 18 + cg * 4];
                ulonglong2 q0 = xr[0];
                ulonglong2 q1 = xr[1];
                ulonglong2 q2 = xr[2];
                ull xv[6] = {q0.x, q0.y, q1.x, q1.y, q2.x, q2.y};
#pragma unroll
                for (int dj = 0; dj < 3; dj++) {
#pragma unroll
                    for (int cr = 0; cr < 2; cr++) {
                        ull wp = *(const ull*)&ws[(co_g * 2 + cr) * WS_STRIDE
                                                  + ci * 9 + di * 3 + dj];
                        fma2(acc[cr][0], wp, xv[dj + 0]);
                        fma2(acc[cr][1], wp, xv[dj + 1]);
                        fma2(acc[cr][2], wp, xv[dj + 2]);
                        fma2(acc[cr][3], wp, xv[dj + 3]);
                    }
                }
            }
        }
    }

    // write out: rows (i0+rp, i0+rp+2), cols j0+cg*4 .. +3
    int r0 = i0 + rp, r1 = i0 + rp + 2;
    int colb = j0 + cg * 4;
#pragma unroll
    for (int cr = 0; cr < 2; cr++) {
        long pb = (long)(zc + co_g * 2 + cr) * Hout * Hout;
#pragma unroll
        for (int c = 0; c < 4; c++) {
            float2 v = up(acc[cr][c]);
            int col = colb + c;
            if (col < Hout) {
                if (r0 < Hout) out[pb + (long)r0 * Hout + col] = fmaxf(v.x, 0.f);
                if (r1 < Hout) out[pb + (long)r1 * Hout + col] = fmaxf(v.y, 0.f);
            }
        }
    }
}

// ---------------- kernel 4: GEMV partials (DRAM-bound, ~81% of peak) ----------------
__global__ void __launch_bounds__(256) gemv_kernel(
    const float* __restrict__ flat, const float* __restrict__ lw,
    float* __restrict__ part) {
    __shared__ __align__(16) float sx[GCHUNK];
    int bc = blockIdx.x;
    long base = (long)bc * GCHUNK;
    int n = FEAT - base;
    if (n > GCHUNK) n = GCHUNK;
    int n4 = n >> 2;

    const float4* xg  = (const float4*)(flat + base);
    float4*       sx4 = (float4*)sx;
    for (int k = threadIdx.x; k < n4; k += 256) sx4[k] = xg[k];
    __syncthreads();

    int wid  = threadIdx.x >> 5;
    int lane = threadIdx.x & 31;
    int rbase = blockIdx.y * 128 + wid * 16;

    for (int g = 0; g < 4; g++) {
        int o = rbase + g * 4;
        const float4* w0 = (const float4*)(lw + (size_t)(o + 0) * FEAT + base);
        const float4* w1 = (const float4*)(lw + (size_t)(o + 1) * FEAT + base);
        const float4* w2 = (const float4*)(lw + (size_t)(o + 2) * FEAT + base);
        const float4* w3 = (const float4*)(lw + (size_t)(o + 3) * FEAT + base);
        float s0 = 0.f, s1 = 0.f, s2 = 0.f, s3 = 0.f;
        for (int k = lane; k < n4; k += 128) {
            float4 a[4][4];
#pragma unroll
            for (int j = 0; j < 4; j++) {
                int kk = k + 32 * j;
                a[0][j] = w0[kk];
                a[1][j] = w1[kk];
                a[2][j] = w2[kk];
                a[3][j] = w3[kk];
            }
#pragma unroll
            for (int j = 0; j < 4; j++) {
                float4 xv = sx4[k + 32 * j];
                s0 = fmaf(a[0][j].x, xv.x, s0); s0 = fmaf(a[0][j].y, xv.y, s0);
                s0 = fmaf(a[0][j].z, xv.z, s0); s0 = fmaf(a[0][j].w, xv.w, s0);
                s1 = fmaf(a[1][j].x, xv.x, s1); s1 = fmaf(a[1][j].y, xv.y, s1);
                s1 = fmaf(a[1][j].z, xv.z, s1); s1 = fmaf(a[1][j].w, xv.w, s1);
                s2 = fmaf(a[2][j].x, xv.x, s2); s2 = fmaf(a[2][j].y, xv.y, s2);
                s2 = fmaf(a[2][j].z, xv.z, s2); s2 = fmaf(a[2][j].w, xv.w, s2);
                s3 = fmaf(a[3][j].x, xv.x, s3); s3 = fmaf(a[3][j].y, xv.y, s3);
                s3 = fmaf(a[3][j].z, xv.z, s3); s3 = fmaf(a[3][j].w, xv.w, s3);
            }
        }
#pragma unroll
        for (int off = 16; off; off >>= 1) {
            s0 += __shfl_xor_sync(0xffffffffu, s0, off);
            s1 += __shfl_xor_sync(0xffffffffu, s1, off);
            s2 += __shfl_xor_sync(0xffffffffu, s2, off);
            s3 += __shfl_xor_sync(0xffffffffu, s3, off);
        }
        if (lane == 0) {
            part[bc * OUTD + o + 0] = s0;
            part[bc * OUTD + o + 1] = s1;
            part[bc * OUTD + o + 2] = s2;
            part[bc * OUTD + o + 3] = s3;
        }
    }
}

// ---------------- kernel 5: parallel deterministic reduce + bias ----------------
__global__ void reduce_kernel(const float* __restrict__ part,
                              const float* __restrict__ lb,
                              float* __restrict__ out) {
    int o = blockIdx.x * 8 + (threadIdx.x >> 5);
    int lane = threadIdx.x & 31;
    float s = 0.f;
    for (int c = lane; c < NBLK; c += 32) s += part[c * OUTD + o];
#pragma unroll
    for (int off = 16; off; off >>= 1)
        s += __shfl_xor_sync(0xffffffffu, s, off);
    if (lane == 0) out[o] = lb[o] + s;
}

// ---------------- launch ----------------
extern "C" void kernel_launch(void* const* d_in, const int* in_sizes, int n_in,
                              void* d_out, int out_size) {
    const int*   x      = (const int*)  d_in[0];
    const float* cat_w  = (const float*)d_in[1];
    const float* cat_b  = (const float*)d_in[2];
    const float* conv_w = (const float*)d_in[3];
    const float* conv_b = (const float*)d_in[4];
    const float* lin_w  = (const float*)d_in[5];
    const float* lin_b  = (const float*)d_in[6];
    float* out = (float*)d_out;

    float *y0, *y1, *y2, *part;
    cudaGetSymbolAddress((void**)&y0,   g_y0);
    cudaGetSymbolAddress((void**)&y1,   g_y1);
    cudaGetSymbolAddress((void**)&y2,   g_y2);
    cudaGetSymbolAddress((void**)&part, g_part);

    dim3 gA((H0 * H0 + 127) / 128, NPC);
    piece_conv<<<gA, 128>>>(x, cat_w, cat_b, y0);

    dim3 g1((H1 + 15) / 16, (H1 + 3) / 4, 2);
    conv3x3<<<g1, 256>>>(y0, conv_w, conv_b, y1, H0, H1);

    dim3 g2((H2 + 15) / 16, (H2 + 3) / 4, 2);
    conv3x3<<<g2, 256>>>(y1, conv_w, conv_b, y2, H1, H2);

    dim3 gg(NBLK, 2);
    gemv_kernel<<<gg, 256>>>(y2, lin_w, part);
    reduce_kernel<<<32, 256>>>(part, lin_b, out);
}